// round 16
// baseline (speedup 1.0000x reference)
#include <cuda_runtime.h>
#include <math.h>

typedef unsigned long long ull;

#define BSZ    64
#define HD     256
#define ED     512
#define VD     32000
#define NGRP   500
#define SOS    1
#define EOS    2
#define MAXLEN 48
#define NEG_INF __int_as_float(0xff800000)

// ---------------- persistent device state ----------------
__device__ int g_alldone;
__device__ ull g_done;
__device__ int g_tok[BSZ];
__device__ __align__(16) float g_encT[256 * BSZ];
__device__ __align__(16) float g_hT0[2][HD * BSZ];   // [h][b]
__device__ __align__(16) float g_hT1[2][HD * BSZ];
__device__ __align__(16) float g_cT0[HD * BSZ];
__device__ __align__(16) float g_cT1[HD * BSZ];
__device__ float g_pval[NGRP * BSZ];
__device__ int   g_pidx[NGRP * BSZ];
// transposed (w,w)-duplicated LSTM weights: dst[k*1024 + r]
__device__ ull g_WiT0[512 * 1024];
__device__ ull g_WhT0[256 * 1024];
__device__ ull g_WiT1[256 * 1024];
__device__ ull g_WhT1[256 * 1024];

// ---------------- helpers ----------------
__device__ __forceinline__ float dsig(float x) {
    return (float)(1.0 / (1.0 + exp(-(double)x)));
}
__device__ __forceinline__ float dth(float x) {
    return (float)tanh((double)x);
}
__device__ __forceinline__ ull ffma2(ull a, ull b, ull c) {
    ull d;
    asm("fma.rn.f32x2 %0, %1, %2, %3;" : "=l"(d) : "l"(a), "l"(b), "l"(c));
    return d;
}
__device__ __forceinline__ float2 unp(ull v) {
    float2 f;
    asm("mov.b64 {%0,%1}, %2;" : "=f"(f.x), "=f"(f.y) : "l"(v));
    return f;
}
__device__ __forceinline__ ull dup2(float w) {
    ull d;
    asm("mov.b64 %0, {%1,%1};" : "=l"(d) : "f"(w));
    return d;
}

// ================= weight duplication =================
extern "C" __global__ void k_dupT(const float* __restrict__ W, ull* __restrict__ dst,
                                  int K, int total) {
    int id = blockIdx.x * 256 + threadIdx.x;
    if (id >= total) return;
    int k = id >> 10, r = id & 1023;
    dst[id] = dup2(W[(size_t)r * K + k]);
}

// ================= pre + init: verbatim R14 =================
extern "C" __global__ void k_pre(const float* __restrict__ enc) {
    int b = blockIdx.x, k = threadIdx.x;
    g_encT[k * BSZ + b] = enc[(size_t)b * 256 + k];
    if (b == 0) {
        if (k < BSZ) g_tok[k] = SOS;
        if (k == 0) { g_done = 0ULL; g_alldone = 0; }
    }
}

extern "C" __global__ void __launch_bounds__(128, 1)
k_init(const float* __restrict__ Wh, const float* __restrict__ bh,
       const float* __restrict__ Wc, const float* __restrict__ bc) {
    int t = threadIdx.x, w = t >> 5, L = t & 31;
    int which = w >> 1, hof = w & 1;
    int h = blockIdx.x * 2 + hof;
    const float* Wr = (which ? Wc : Wh) + (size_t)h * 256;
    float ax = 0.f, ay = 0.f;
#pragma unroll 4
    for (int k = 0; k < 256; k += 4) {
        float4 wv = *(const float4*)(Wr + k);
        float2 x0 = *(const float2*)&g_encT[(k + 0) * BSZ + 2 * L];
        float2 x1 = *(const float2*)&g_encT[(k + 1) * BSZ + 2 * L];
        float2 x2 = *(const float2*)&g_encT[(k + 2) * BSZ + 2 * L];
        float2 x3 = *(const float2*)&g_encT[(k + 3) * BSZ + 2 * L];
        ax = fmaf(wv.x, x0.x, ax); ay = fmaf(wv.x, x0.y, ay);
        ax = fmaf(wv.y, x1.x, ax); ay = fmaf(wv.y, x1.y, ay);
        ax = fmaf(wv.z, x2.x, ax); ay = fmaf(wv.z, x2.y, ay);
        ax = fmaf(wv.w, x3.x, ax); ay = fmaf(wv.w, x3.y, ay);
    }
    float bb = which ? bc[h] : bh[h];
    float2 v = make_float2(ax + bb, ay + bb);
    int idx = h * BSZ + 2 * L;
    if (which == 0) { *(float2*)&g_hT0[0][idx] = v; *(float2*)&g_hT1[0][idx] = v; }
    else            { *(float2*)&g_cT0[idx]    = v; *(float2*)&g_cT1[idx]    = v; }
}

// ================= fused LSTM, f32x2, high parallelism =================
// grid 256 = 32 hgroups x 8 bgroups; 128 threads = 4 warps.
// warp w = batch-pair p (batches b0+2w, b0+2w+1); lane L: gate = L>>3, hl = L&7.
// Row r = gate*256 + hg*8 + hl. One serial chain per output (Wih over Ei then
// Whh over 256, then +(bih+bhh)) == R14/R15 numerics (validated rel_err 0.0).
extern "C" __global__ void __launch_bounds__(128, 2)
k_lstm(const ull* __restrict__ WiT, const ull* __restrict__ WhT,
       const float* __restrict__ bih, const float* __restrict__ bhh,
       const float* __restrict__ emb, int layer, int par)
{
    __shared__ ull xs2[512 * 4];     // [k][pair] packed (x_b, x_{b+1}); 16KB
    __shared__ ull hs2[256 * 4];     // 8KB
    __shared__ float gall[4 * 8 * 8];  // [gate][hl][b_loc]

    const int tid = threadIdx.x;
    const int w = tid >> 5, L = tid & 31;
    const int gate = L >> 3, hl = L & 7;
    const int hg = blockIdx.x >> 3, bg = blockIdx.x & 7;
    const int b0 = bg * 8;
    const int r = gate * HD + hg * 8 + hl;
    const int Ei = (layer == 0) ? ED : HD;

    // ---- stage x ----
    if (layer == 0) {
        float* xf = (float*)xs2;   // [k][8] scalar view, pair p = cols 2p,2p+1
        for (int j = 0; j < 8; j++) {
            const float* row = emb + (size_t)g_tok[b0 + j] * ED;
            float4 v = ((const float4*)row)[tid];   // tid < 128 covers 512
            int k = tid * 4;
            xf[k * 8 + j] = v.x; xf[(k + 1) * 8 + j] = v.y;
            xf[(k + 2) * 8 + j] = v.z; xf[(k + 3) * 8 + j] = v.w;
        }
    } else {
        const float* src = g_hT0[par ^ 1];
        for (int i = tid; i < 1024; i += 128) {
            int k = i >> 2, p = i & 3;
            float2 v = *(const float2*)&src[k * 64 + b0 + 2 * p];
            xs2[k * 4 + p] = *(ull*)&v;
        }
    }
    // ---- stage hprev ----
    {
        const float* hpv = (layer == 0) ? g_hT0[par] : g_hT1[par];
        for (int i = tid; i < 1024; i += 128) {
            int k = i >> 2, p = i & 3;
            float2 v = *(const float2*)&hpv[k * 64 + b0 + 2 * p];
            hs2[k * 4 + p] = *(ull*)&v;
        }
    }
    __syncthreads();

    // ---- gate chain (serial, verbatim order) ----
    ull acc = 0ULL;
#pragma unroll 16
    for (int k = 0; k < Ei; k++)
        acc = ffma2(xs2[k * 4 + w], WiT[(size_t)k * 1024 + r], acc);
#pragma unroll 16
    for (int k = 0; k < HD; k++)
        acc = ffma2(hs2[k * 4 + w], WhT[(size_t)k * 1024 + r], acc);

    float bb = bih[r] + bhh[r];
    float2 f = unp(acc);
    gall[gate * 64 + hl * 8 + 2 * w]     = f.x + bb;
    gall[gate * 64 + hl * 8 + 2 * w + 1] = f.y + bb;
    __syncthreads();

    // ---- cell (verbatim R14 math) ----
    if (tid < 64) {
        int hl2 = tid >> 3, bj = tid & 7;
        float gi = gall[0 * 64 + hl2 * 8 + bj];
        float gf = gall[1 * 64 + hl2 * 8 + bj];
        float gg = gall[2 * 64 + hl2 * 8 + bj];
        float go = gall[3 * 64 + hl2 * 8 + bj];
        float* cT   = (layer == 0) ? g_cT0 : g_cT1;
        float* hout = (layer == 0) ? g_hT0[par ^ 1] : g_hT1[par ^ 1];
        int idx = (hg * 8 + hl2) * 64 + b0 + bj;
        float c  = cT[idx];
        float cn = dsig(gf) * c + dsig(gi) * dth(gg);
        cT[idx] = cn;
        hout[idx] = dsig(go) * dth(cn);
    }
}

// ================= logits + per-block argmax: verbatim R14 (proven) ========
extern "C" __global__ void __launch_bounds__(256, 1)
k_logits(const float* __restrict__ Wout, const float* __restrict__ bout, int par) {
    __shared__ float h1s[128 * BSZ];     // 32 KB
    __shared__ float redv[8 * BSZ];
    __shared__ int   redi[8 * BSZ];
    int t = threadIdx.x, w = t >> 5, L = t & 31, grp = blockIdx.x;
    const float* h1g = g_hT1[par ^ 1];

    float2 acc[8];
#pragma unroll
    for (int v = 0; v < 8; v++) acc[v] = make_float2(0.f, 0.f);

    for (int half = 0; half < 2; half++) {
        __syncthreads();
        for (int i = t; i < 2048; i += 256)
            ((float4*)h1s)[i] = ((const float4*)(h1g + half * 128 * BSZ))[i];
        __syncthreads();
        const float* wbase = Wout + (size_t)(grp * 64 + w * 8) * HD + half * 128;
#pragma unroll 1
        for (int k4 = 0; k4 < 32; k4++) {
            float4 wv[8];
#pragma unroll
            for (int v = 0; v < 8; v++)
                wv[v] = *(const float4*)(wbase + (size_t)v * HD + k4 * 4);
#pragma unroll
            for (int j = 0; j < 4; j++) {
                float2 hv = *(const float2*)&h1s[(k4 * 4 + j) * BSZ + 2 * L];
#pragma unroll
                for (int v = 0; v < 8; v++) {
                    float wj = (j == 0) ? wv[v].x : (j == 1) ? wv[v].y
                             : (j == 2) ? wv[v].z : wv[v].w;
                    acc[v].x = fmaf(wj, hv.x, acc[v].x);
                    acc[v].y = fmaf(wj, hv.y, acc[v].y);
                }
            }
        }
    }

    int vbase = grp * 64 + w * 8;
    float bvx = NEG_INF, bvy = NEG_INF;
    int bix = 0, biy = 0;
#pragma unroll
    for (int v = 0; v < 8; v++) {
        float bo = bout[vbase + v];
        float sx = acc[v].x + bo, sy = acc[v].y + bo;
        if (sx > bvx) { bvx = sx; bix = vbase + v; }
        if (sy > bvy) { bvy = sy; biy = vbase + v; }
    }
    redv[w * BSZ + 2 * L]     = bvx; redi[w * BSZ + 2 * L]     = bix;
    redv[w * BSZ + 2 * L + 1] = bvy; redi[w * BSZ + 2 * L + 1] = biy;
    __syncthreads();
    if (t < BSZ) {
        float bv = redv[t]; int bi = redi[t];
#pragma unroll
        for (int w2 = 1; w2 < 8; w2++) {
            float v = redv[w2 * BSZ + t]; int i2 = redi[w2 * BSZ + t];
            if (v > bv || (v == bv && i2 < bi)) { bv = v; bi = i2; }
        }
        g_pval[grp * BSZ + t] = bv;
        g_pidx[grp * BSZ + t] = bi;
    }
}

// ================= global argmax + token logic: verbatim R14 =================
extern "C" __global__ void __launch_bounds__(256, 1)
k_reduce(float* __restrict__ outp, int step) {
    __shared__ float redv[4 * BSZ];
    __shared__ int   redi[4 * BSZ];
    __shared__ unsigned sball[2];
    int t = threadIdx.x, b = t & 63, q = t >> 6;

    float bv = NEG_INF; int bi = 0x7fffffff;
    for (int p = q * 125; p < q * 125 + 125; p++) {
        float v = g_pval[p * BSZ + b]; int i2 = g_pidx[p * BSZ + b];
        if (v > bv || (v == bv && i2 < bi)) { bv = v; bi = i2; }
    }
    redv[q * BSZ + b] = bv; redi[q * BSZ + b] = bi;
    int adp = g_alldone;
    ull pdm = g_done;
    __syncthreads();
    if (t < BSZ) {
        bv = redv[t]; bi = redi[t];
#pragma unroll
        for (int q2 = 1; q2 < 4; q2++) {
            float v = redv[q2 * BSZ + t]; int i2 = redi[q2 * BSZ + t];
            if (v > bv || (v == bv && i2 < bi)) { bv = v; bi = i2; }
        }
        int out = adp ? 0 : bi;
        outp[t * MAXLEN + step] = (float)out;
        g_tok[t] = out;
        int nd = (int)((pdm >> t) & 1ULL) | (out == EOS);
        unsigned bal = __ballot_sync(0xffffffffu, nd != 0);
        if ((t & 31) == 0) sball[t >> 5] = bal;
    }
    __syncthreads();
    if (t == 0) {
        ull nm = (ull)sball[0] | ((ull)sball[1] << 32);
        g_done = nm;
        g_alldone = adp | (nm == 0xFFFFFFFFFFFFFFFFULL);
    }
}

// ================= host =================
static void* devptr(const void* sym) {
    void* p = 0; cudaGetSymbolAddress(&p, sym); return p;
}

extern "C" void kernel_launch(void* const* d_in, const int* in_sizes, int n_in,
                              void* d_out, int out_size) {
    (void)in_sizes; (void)n_in; (void)out_size;
    const float* enc  = (const float*)d_in[0];
    const float* emb  = (const float*)d_in[1];
    const float* Wh   = (const float*)d_in[2];
    const float* bh   = (const float*)d_in[3];
    const float* Wc   = (const float*)d_in[4];
    const float* bc   = (const float*)d_in[5];
    const float* Wih0 = (const float*)d_in[6];
    const float* Whh0 = (const float*)d_in[7];
    const float* bih0 = (const float*)d_in[8];
    const float* bhh0 = (const float*)d_in[9];
    const float* Wih1 = (const float*)d_in[10];
    const float* Whh1 = (const float*)d_in[11];
    const float* bih1 = (const float*)d_in[12];
    const float* bhh1 = (const float*)d_in[13];
    const float* Wout = (const float*)d_in[14];
    const float* bout = (const float*)d_in[15];
    float*       outp = (float*)d_out;

    ull* WiT0 = (ull*)devptr((const void*)g_WiT0);
    ull* WhT0 = (ull*)devptr((const void*)g_WhT0);
    ull* WiT1 = (ull*)devptr((const void*)g_WiT1);
    ull* WhT1 = (ull*)devptr((const void*)g_WhT1);

    k_dupT<<<2048, 256>>>(Wih0, WiT0, 512, 512 * 1024);
    k_dupT<<<1024, 256>>>(Whh0, WhT0, 256, 256 * 1024);
    k_dupT<<<1024, 256>>>(Wih1, WiT1, 256, 256 * 1024);
    k_dupT<<<1024, 256>>>(Whh1, WhT1, 256, 256 * 1024);

    k_pre<<<64, 256>>>(enc);
    k_init<<<128, 128>>>(Wh, bh, Wc, bc);

    for (int s = 0; s < MAXLEN; s++) {
        int par = s & 1;
        k_lstm<<<256, 128>>>(WiT0, WhT0, bih0, bhh0, emb, 0, par);
        k_lstm<<<256, 128>>>(WiT1, WhT1, bih1, bhh1, emb, 1, par);
        k_logits<<<NGRP, 256>>>(Wout, bout, par);
        k_reduce<<<1, 256>>>(outp, s);
    }
}

// round 17
// speedup vs baseline: 1.3401x; 1.3401x over previous
#include <cuda_runtime.h>
#include <math.h>

typedef unsigned long long ull;

#define BSZ    64
#define HD     256
#define ED     512
#define VD     32000
#define NGRP   500
#define SOS    1
#define EOS    2
#define MAXLEN 48
#define NEG_INF __int_as_float(0xff800000)

// ---------------- persistent device state ----------------
__device__ int g_alldone;
__device__ ull g_done;
__device__ int g_tok[BSZ];
__device__ __align__(16) float g_encT[256 * BSZ];
__device__ __align__(16) float g_xT[ED * BSZ];       // [k][b]
__device__ __align__(16) float g_hT0[2][HD * BSZ];   // [h][b]
__device__ __align__(16) float g_hT1[2][HD * BSZ];
__device__ __align__(16) float g_cT0[HD * BSZ];
__device__ __align__(16) float g_cT1[HD * BSZ];
__device__ float g_pval[NGRP * BSZ];
__device__ int   g_pidx[NGRP * BSZ];
__device__ ull   g_Wod[(size_t)VD * 256];            // (w,w)-dup Wout, 65.5MB

// ---------------- helpers ----------------
__device__ __forceinline__ float dsig(float x) {
    return (float)(1.0 / (1.0 + exp(-(double)x)));
}
__device__ __forceinline__ float dth(float x) {
    return (float)tanh((double)x);
}
__device__ __forceinline__ ull ffma2(ull a, ull b, ull c) {
    ull d;
    asm("fma.rn.f32x2 %0, %1, %2, %3;" : "=l"(d) : "l"(a), "l"(b), "l"(c));
    return d;
}
__device__ __forceinline__ float2 unp(ull v) {
    float2 f;
    asm("mov.b64 {%0,%1}, %2;" : "=f"(f.x), "=f"(f.y) : "l"(v));
    return f;
}
__device__ __forceinline__ ull dup2(float w) {
    ull d;
    asm("mov.b64 %0, {%1,%1};" : "=l"(d) : "f"(w));
    return d;
}

// ================= Wout duplication =================
extern "C" __global__ void k_dupO(const float* __restrict__ W) {
    size_t id = (size_t)blockIdx.x * 256 + threadIdx.x;
    if (id < (size_t)VD * 256) g_Wod[id] = dup2(W[id]);
}

// ================= pre + init + gather: verbatim R14 =================
extern "C" __global__ void k_pre(const float* __restrict__ enc) {
    int b = blockIdx.x, k = threadIdx.x;
    g_encT[k * BSZ + b] = enc[(size_t)b * 256 + k];
    if (b == 0) {
        if (k < BSZ) g_tok[k] = SOS;
        if (k == 0) { g_done = 0ULL; g_alldone = 0; }
    }
}

extern "C" __global__ void __launch_bounds__(128, 1)
k_init(const float* __restrict__ Wh, const float* __restrict__ bh,
       const float* __restrict__ Wc, const float* __restrict__ bc) {
    int t = threadIdx.x, w = t >> 5, L = t & 31;
    int which = w >> 1, hof = w & 1;
    int h = blockIdx.x * 2 + hof;
    const float* Wr = (which ? Wc : Wh) + (size_t)h * 256;
    float ax = 0.f, ay = 0.f;
#pragma unroll 4
    for (int k = 0; k < 256; k += 4) {
        float4 wv = *(const float4*)(Wr + k);
        float2 x0 = *(const float2*)&g_encT[(k + 0) * BSZ + 2 * L];
        float2 x1 = *(const float2*)&g_encT[(k + 1) * BSZ + 2 * L];
        float2 x2 = *(const float2*)&g_encT[(k + 2) * BSZ + 2 * L];
        float2 x3 = *(const float2*)&g_encT[(k + 3) * BSZ + 2 * L];
        ax = fmaf(wv.x, x0.x, ax); ay = fmaf(wv.x, x0.y, ay);
        ax = fmaf(wv.y, x1.x, ax); ay = fmaf(wv.y, x1.y, ay);
        ax = fmaf(wv.z, x2.x, ax); ay = fmaf(wv.z, x2.y, ay);
        ax = fmaf(wv.w, x3.x, ax); ay = fmaf(wv.w, x3.y, ay);
    }
    float bb = which ? bc[h] : bh[h];
    float2 v = make_float2(ax + bb, ay + bb);
    int idx = h * BSZ + 2 * L;
    if (which == 0) { *(float2*)&g_hT0[0][idx] = v; *(float2*)&g_hT1[0][idx] = v; }
    else            { *(float2*)&g_cT0[idx]    = v; *(float2*)&g_cT1[idx]    = v; }
}

extern "C" __global__ void k_gather(const float* __restrict__ emb) {
    int b = blockIdx.x, t = threadIdx.x;
    const float* row = emb + (size_t)g_tok[b] * ED;
    g_xT[t * BSZ + b]         = row[t];
    g_xT[(t + 256) * BSZ + b] = row[t + 256];
}

// ================= LSTM: R14 mapping + smem-staged x/h =================
// grid 128, 256 threads: warp w: gate=w>>1, hof=w&1; lane L -> b {2L,2L+1}.
// Row r = gate*HD + h. W loads warp-broadcast (R14-proven). x/h staged in
// 32KB k-tiles. Chain order identical to R14 (x over Ei, then h, then bias).
extern "C" __global__ void __launch_bounds__(256, 2)
k_lstm(const float* __restrict__ Wih, const float* __restrict__ Whh,
       const float* __restrict__ bih, const float* __restrict__ bhh,
       int layer, int par) {
    __shared__ float ts[128 * BSZ];      // 32KB tile
    __shared__ float gsm[4][2][BSZ];
    int t = threadIdx.x, w = t >> 5, L = t & 31;
    int gate = w >> 1, hof = w & 1;
    int h = blockIdx.x * 2 + hof;
    int r = gate * HD + h;

    const float* xsrc; const float* hsrc; float* hout; float* cT; int Ei;
    if (layer == 0) { xsrc = g_xT;           Ei = ED; hsrc = g_hT0[par]; hout = g_hT0[par ^ 1]; cT = g_cT0; }
    else            { xsrc = g_hT0[par ^ 1]; Ei = HD; hsrc = g_hT1[par]; hout = g_hT1[par ^ 1]; cT = g_cT1; }

    float ax = 0.f, ay = 0.f;

    // phase 1: x over Ei
    const float* Wr1 = Wih + (size_t)r * Ei;
    for (int t0 = 0; t0 < Ei; t0 += 128) {
        __syncthreads();
        for (int i = t; i < 2048; i += 256)
            ((float4*)ts)[i] = ((const float4*)(xsrc + t0 * BSZ))[i];
        __syncthreads();
#pragma unroll 8
        for (int kk = 0; kk < 128; kk += 4) {
            float4 wv = *(const float4*)(Wr1 + t0 + kk);
            float2 x0 = *(const float2*)&ts[(kk + 0) * BSZ + 2 * L];
            float2 x1 = *(const float2*)&ts[(kk + 1) * BSZ + 2 * L];
            float2 x2 = *(const float2*)&ts[(kk + 2) * BSZ + 2 * L];
            float2 x3 = *(const float2*)&ts[(kk + 3) * BSZ + 2 * L];
            ax = fmaf(wv.x, x0.x, ax); ay = fmaf(wv.x, x0.y, ay);
            ax = fmaf(wv.y, x1.x, ax); ay = fmaf(wv.y, x1.y, ay);
            ax = fmaf(wv.z, x2.x, ax); ay = fmaf(wv.z, x2.y, ay);
            ax = fmaf(wv.w, x3.x, ax); ay = fmaf(wv.w, x3.y, ay);
        }
    }
    // phase 2: h over 256
    const float* Wr2 = Whh + (size_t)r * HD;
    for (int t0 = 0; t0 < HD; t0 += 128) {
        __syncthreads();
        for (int i = t; i < 2048; i += 256)
            ((float4*)ts)[i] = ((const float4*)(hsrc + t0 * BSZ))[i];
        __syncthreads();
#pragma unroll 8
        for (int kk = 0; kk < 128; kk += 4) {
            float4 wv = *(const float4*)(Wr2 + t0 + kk);
            float2 x0 = *(const float2*)&ts[(kk + 0) * BSZ + 2 * L];
            float2 x1 = *(const float2*)&ts[(kk + 1) * BSZ + 2 * L];
            float2 x2 = *(const float2*)&ts[(kk + 2) * BSZ + 2 * L];
            float2 x3 = *(const float2*)&ts[(kk + 3) * BSZ + 2 * L];
            ax = fmaf(wv.x, x0.x, ax); ay = fmaf(wv.x, x0.y, ay);
            ax = fmaf(wv.y, x1.x, ax); ay = fmaf(wv.y, x1.y, ay);
            ax = fmaf(wv.z, x2.x, ax); ay = fmaf(wv.z, x2.y, ay);
            ax = fmaf(wv.w, x3.x, ax); ay = fmaf(wv.w, x3.y, ay);
        }
    }

    float bb = bih[r] + bhh[r];
    *(float2*)&gsm[gate][hof][2 * L] = make_float2(ax + bb, ay + bb);
    __syncthreads();

    if (t < 128) {
        int ho = t >> 6, b = t & 63;
        int hh = blockIdx.x * 2 + ho;
        float gi = gsm[0][ho][b], gf = gsm[1][ho][b];
        float gg = gsm[2][ho][b], go = gsm[3][ho][b];
        int idx = hh * BSZ + b;
        float c  = cT[idx];
        float cn = dsig(gf) * c + dsig(gi) * dth(gg);
        cT[idx] = cn;
        hout[idx] = dsig(go) * dth(cn);
    }
}

// ================= logits + argmax: R15's f32x2 version (proven) ===========
extern "C" __global__ void __launch_bounds__(256, 1)
k_logits(const float* __restrict__ bout, int par) {
    __shared__ ull  h1s[128 * 32];       // 32KB: [k][32 pairs]
    __shared__ float redv[8 * BSZ];
    __shared__ int   redi[8 * BSZ];
    int t = threadIdx.x, w = t >> 5, L = t & 31, grp = blockIdx.x;
    const float* h1g = g_hT1[par ^ 1];

    ull acc[8];
#pragma unroll
    for (int v = 0; v < 8; v++) acc[v] = 0ULL;

    const int vbase = grp * 64 + w * 8;
    const ull* wb = g_Wod + (size_t)vbase * 256;

    for (int half = 0; half < 2; half++) {
        __syncthreads();
        for (int i = t; i < 2048; i += 256)
            ((float4*)h1s)[i] = ((const float4*)(h1g + half * 128 * BSZ))[i];
        __syncthreads();
        const ull* wh = wb + half * 128;
#pragma unroll 2
        for (int k2 = 0; k2 < 64; k2++) {
            ull hq0 = h1s[(2 * k2) * 32 + L];
            ull hq1 = h1s[(2 * k2 + 1) * 32 + L];
#pragma unroll
            for (int v = 0; v < 8; v++) {
                ulonglong2 wd = *(const ulonglong2*)(wh + (size_t)v * 256 + 2 * k2);
                acc[v] = ffma2(hq0, wd.x, acc[v]);
                acc[v] = ffma2(hq1, wd.y, acc[v]);
            }
        }
    }

    float bvx = NEG_INF, bvy = NEG_INF;
    int bix = 0, biy = 0;
#pragma unroll
    for (int v = 0; v < 8; v++) {
        float bo = bout[vbase + v];
        float2 f = unp(acc[v]);
        float sx = f.x + bo, sy = f.y + bo;
        if (sx > bvx) { bvx = sx; bix = vbase + v; }
        if (sy > bvy) { bvy = sy; biy = vbase + v; }
    }
    redv[w * BSZ + 2 * L]     = bvx; redi[w * BSZ + 2 * L]     = bix;
    redv[w * BSZ + 2 * L + 1] = bvy; redi[w * BSZ + 2 * L + 1] = biy;
    __syncthreads();
    if (t < BSZ) {
        float bv = redv[t]; int bi = redi[t];
#pragma unroll
        for (int w2 = 1; w2 < 8; w2++) {
            float v = redv[w2 * BSZ + t]; int i2 = redi[w2 * BSZ + t];
            if (v > bv || (v == bv && i2 < bi)) { bv = v; bi = i2; }
        }
        g_pval[grp * BSZ + t] = bv;
        g_pidx[grp * BSZ + t] = bi;
    }
}

// ================= global argmax + token logic: verbatim R14 =================
extern "C" __global__ void __launch_bounds__(256, 1)
k_reduce(float* __restrict__ outp, int step) {
    __shared__ float redv[4 * BSZ];
    __shared__ int   redi[4 * BSZ];
    __shared__ unsigned sball[2];
    int t = threadIdx.x, b = t & 63, q = t >> 6;

    float bv = NEG_INF; int bi = 0x7fffffff;
    for (int p = q * 125; p < q * 125 + 125; p++) {
        float v = g_pval[p * BSZ + b]; int i2 = g_pidx[p * BSZ + b];
        if (v > bv || (v == bv && i2 < bi)) { bv = v; bi = i2; }
    }
    redv[q * BSZ + b] = bv; redi[q * BSZ + b] = bi;
    int adp = g_alldone;
    ull pdm = g_done;
    __syncthreads();
    if (t < BSZ) {
        bv = redv[t]; bi = redi[t];
#pragma unroll
        for (int q2 = 1; q2 < 4; q2++) {
            float v = redv[q2 * BSZ + t]; int i2 = redi[q2 * BSZ + t];
            if (v > bv || (v == bv && i2 < bi)) { bv = v; bi = i2; }
        }
        int out = adp ? 0 : bi;
        outp[t * MAXLEN + step] = (float)out;
        g_tok[t] = out;
        int nd = (int)((pdm >> t) & 1ULL) | (out == EOS);
        unsigned bal = __ballot_sync(0xffffffffu, nd != 0);
        if ((t & 31) == 0) sball[t >> 5] = bal;
    }
    __syncthreads();
    if (t == 0) {
        ull nm = (ull)sball[0] | ((ull)sball[1] << 32);
        g_done = nm;
        g_alldone = adp | (nm == 0xFFFFFFFFFFFFFFFFULL);
    }
}

// ================= host =================
extern "C" void kernel_launch(void* const* d_in, const int* in_sizes, int n_in,
                              void* d_out, int out_size) {
    (void)in_sizes; (void)n_in; (void)out_size;
    const float* enc  = (const float*)d_in[0];
    const float* emb  = (const float*)d_in[1];
    const float* Wh   = (const float*)d_in[2];
    const float* bh   = (const float*)d_in[3];
    const float* Wc   = (const float*)d_in[4];
    const float* bc   = (const float*)d_in[5];
    const float* Wih0 = (const float*)d_in[6];
    const float* Whh0 = (const float*)d_in[7];
    const float* bih0 = (const float*)d_in[8];
    const float* bhh0 = (const float*)d_in[9];
    const float* Wih1 = (const float*)d_in[10];
    const float* Whh1 = (const float*)d_in[11];
    const float* bih1 = (const float*)d_in[12];
    const float* bhh1 = (const float*)d_in[13];
    const float* Wout = (const float*)d_in[14];
    const float* bout = (const float*)d_in[15];
    float*       outp = (float*)d_out;

    k_dupO<<<32000, 256>>>(Wout);
    k_pre<<<64, 256>>>(enc);
    k_init<<<128, 128>>>(Wh, bh, Wc, bc);

    for (int s = 0; s < MAXLEN; s++) {
        int par = s & 1;
        k_gather<<<64, 256>>>(emb);
        k_lstm<<<128, 256>>>(Wih0, Whh0, bih0, bhh0, 0, par);
        k_lstm<<<128, 256>>>(Wih1, Whh1, bih1, bhh1, 1, par);
        k_logits<<<NGRP, 256>>>(bout, par);
        k_reduce<<<1, 256>>>(outp, s);
    }
}